// round 4
// baseline (speedup 1.0000x reference)
#include <cuda_runtime.h>

#define THREADS 256
#define ITEMS 16
#define TILE (THREADS * ITEMS)   // 4096
#define MAX_TILES 65536
#define NWARPS (THREADS / 32)

// decoupled-lookback state: high 32 bits = epoch*4 + status (1=aggregate, 2=prefix),
// low 32 bits = fp32 value bits. Flag+value in one 64-bit word => relaxed ld/st OK.
// Epoch versioning means NO init kernel: stale words from the previous launch
// decode as invalid for the current epoch.
__device__ unsigned long long g_state[MAX_TILES];
__device__ unsigned int g_ticket;   // zero-initialized once; monotonic across replays

__device__ __forceinline__ unsigned long long ld_state(const unsigned long long* p) {
    unsigned long long v;
    asm volatile("ld.global.cg.u64 %0, [%1];" : "=l"(v) : "l"(p));
    return v;
}
__device__ __forceinline__ void st_state(unsigned long long* p, unsigned long long v) {
    asm volatile("st.global.cg.u64 [%0], %1;" :: "l"(p), "l"(v) : "memory");
}
__device__ __forceinline__ unsigned long long pack_sv(unsigned st, float v) {
    return ((unsigned long long)st << 32) | (unsigned long long)__float_as_uint(v);
}

__global__ void __launch_bounds__(THREADS, 6) rtam_scan(
    const int* __restrict__ ann,
    const float* __restrict__ p_origin,
    const float* __restrict__ p_bd,
    const float* __restrict__ p_d,
    const float* __restrict__ p_s,
    const float* __restrict__ p_inc,
    const float* __restrict__ p_bi,
    float* __restrict__ out,
    int n, int ntiles)
{
    __shared__ float s_table[8];
    __shared__ float s_warp[NWARPS];
    __shared__ float s_excl;
    __shared__ unsigned s_ticket;

    const int tid  = threadIdx.x;
    const int lane = tid & 31;
    const int wid  = tid >> 5;

    if (tid == 0) {
        s_ticket = atomicAdd(&g_ticket, 1u);
        const float EPS = 0.05f;
        float bd = *p_bd, d = *p_d, s = *p_s, inc = *p_inc, bi = *p_bi;
        s_table[0] = 0.f;
        s_table[1] = fminf(bd, fminf(0.f, d)) - EPS;                 // big decrease
        s_table[2] = fminf(fmaxf(d, bd + EPS), -EPS);                // decrease (clip)
        s_table[3] = s;                                              // same
        s_table[4] = fminf(fmaxf(inc, EPS), bi - EPS);               // increase (clip)
        s_table[5] = fmaxf(bi, fmaxf(0.f, inc) + EPS);               // big increase
        s_table[6] = *p_origin;
    }
    __syncthreads();

    const unsigned ticket = s_ticket;
    const unsigned tile   = ticket % (unsigned)ntiles;
    const unsigned epoch  = ticket / (unsigned)ntiles;
    const unsigned eb     = epoch * 4u;               // status base for this epoch
    const float origin    = s_table[6];
    const long long base  = (long long)tile * TILE;
    const long long rem64 = (long long)n - base;
    const int remaining   = (rem64 > (long long)TILE) ? TILE : (int)rem64;

    // ---- per-thread blocked load + serial inclusive scan (16 items) ----
    float vals[ITEMS];
    float run = 0.f;

    if (remaining >= TILE) {
        const int4* in4 = (const int4*)(ann + base);
        #pragma unroll
        for (int k = 0; k < ITEMS / 4; k++) {
            int4 c = in4[tid * (ITEMS / 4) + k];
            run += s_table[c.x]; vals[4 * k + 0] = run;
            run += s_table[c.y]; vals[4 * k + 1] = run;
            run += s_table[c.z]; vals[4 * k + 2] = run;
            run += s_table[c.w]; vals[4 * k + 3] = run;
        }
    } else {
        #pragma unroll
        for (int j = 0; j < ITEMS; j++) {
            long long idx = base + (long long)tid * ITEMS + j;
            float c = (idx < (long long)n) ? s_table[ann[idx]] : 0.f;
            run += c;
            vals[j] = run;
        }
    }

    // ---- block scan of per-thread sums (warp shfl + smem across warps) ----
    const float tsum = run;
    float x = tsum;
    #pragma unroll
    for (int o = 1; o < 32; o <<= 1) {
        float y = __shfl_up_sync(0xFFFFFFFFu, x, o);
        if (lane >= o) x += y;
    }
    if (lane == 31) s_warp[wid] = x;
    __syncthreads();
    if (wid == 0) {
        float w = (lane < NWARPS) ? s_warp[lane] : 0.f;
        #pragma unroll
        for (int o = 1; o < NWARPS; o <<= 1) {
            float y = __shfl_up_sync(0xFFFFFFFFu, w, o);
            if (lane >= o) w += y;
        }
        if (lane < NWARPS) s_warp[lane] = w;
    }
    __syncthreads();

    const float block_agg   = s_warp[NWARPS - 1];
    const float thread_excl = (wid > 0 ? s_warp[wid - 1] : 0.f) + (x - tsum);

    // ---- warp 0: publish aggregate, decoupled lookback, publish prefix ----
    if (wid == 0) {
        if (lane == 0)
            st_state(&g_state[tile], pack_sv(eb + (tile == 0 ? 2u : 1u), block_agg));

        float excl = 0.f;
        if (tile > 0) {
            int look = (int)tile - 1;
            for (;;) {
                int idx = look - lane;
                unsigned d;       // 1 = aggregate, 2 = prefix, else invalid
                float val;
                if (idx >= 0) {
                    unsigned long long v = ld_state(&g_state[idx]);
                    d   = (unsigned)(v >> 32) - eb;   // wraps to huge if stale epoch
                    val = __uint_as_float((unsigned)(v & 0xFFFFFFFFULL));
                } else {
                    d = 2u; val = 0.f;
                }
                unsigned pm = __ballot_sync(0xFFFFFFFFu, d == 2u);
                unsigned am = __ballot_sync(0xFFFFFFFFu, d == 1u || d == 2u);
                if (pm) {
                    int p = __ffs(pm) - 1;   // closest predecessor with a full prefix
                    unsigned need = (p == 31) ? 0xFFFFFFFFu : ((1u << (p + 1)) - 1u);
                    if ((am & need) == need) {
                        float contrib = (lane <= p) ? val : 0.f;
                        #pragma unroll
                        for (int o = 16; o; o >>= 1)
                            contrib += __shfl_xor_sync(0xFFFFFFFFu, contrib, o);
                        excl += contrib;
                        break;
                    }
                } else if (am == 0xFFFFFFFFu) {
                    float contrib = val;     // window of 32 aggregates, keep walking
                    #pragma unroll
                    for (int o = 16; o; o >>= 1)
                        contrib += __shfl_xor_sync(0xFFFFFFFFu, contrib, o);
                    excl += contrib;
                    look -= 32;
                }
                // else: spin until predecessors publish
            }
            if (lane == 0)
                st_state(&g_state[tile], pack_sv(eb + 2u, excl + block_agg));
        }
        if (lane == 0) s_excl = excl;
    }
    __syncthreads();

    const float pref = origin + s_excl + thread_excl;

    // ---- direct blocked stores: thread covers out[base+16*tid+1 .. +16] ----
    if (remaining >= TILE) {
        float* p = out + base + tid * ITEMS;   // p is 16B-aligned
        p[1] = pref + vals[0];
        float2 h; h.x = pref + vals[1]; h.y = pref + vals[2];
        *(float2*)(p + 2) = h;                 // 8B-aligned
        #pragma unroll
        for (int k = 0; k < 3; k++) {
            float4 r;
            r.x = pref + vals[3 + 4 * k];
            r.y = pref + vals[4 + 4 * k];
            r.z = pref + vals[5 + 4 * k];
            r.w = pref + vals[6 + 4 * k];
            *(float4*)(p + 4 + 4 * k) = r;     // 16B-aligned
        }
        p[16] = pref + vals[15];
    } else {
        #pragma unroll
        for (int j = 0; j < ITEMS; j++) {
            int i = tid * ITEMS + j;
            if (i < remaining) out[base + 1 + i] = pref + vals[j];
        }
    }

    if (tile == 0 && tid == 0) out[0] = origin;
}

extern "C" void kernel_launch(void* const* d_in, const int* in_sizes, int n_in,
                              void* d_out, int out_size) {
    const int*   ann    = (const int*)d_in[0];
    const float* origin = (const float*)d_in[1];
    const float* bd     = (const float*)d_in[2];
    const float* d      = (const float*)d_in[3];
    const float* s      = (const float*)d_in[4];
    const float* inc    = (const float*)d_in[5];
    const float* bi     = (const float*)d_in[6];
    float* out = (float*)d_out;

    int n = in_sizes[0];
    int ntiles = (n + TILE - 1) / TILE;
    if (ntiles > MAX_TILES) ntiles = MAX_TILES;   // n = 2^25 -> 8192 tiles

    rtam_scan<<<ntiles, THREADS>>>(ann, origin, bd, d, s, inc, bi, out, n, ntiles);
}

// round 5
// speedup vs baseline: 1.1602x; 1.1602x over previous
#include <cuda_runtime.h>

#define THREADS 512
#define ITEMS 16
#define TILE (THREADS * ITEMS)   // 8192
#define MAX_TILES 65536
#define NWARPS (THREADS / 32)

// decoupled-lookback state: high 32 bits = epoch*4 + status (1=aggregate, 2=prefix),
// low 32 bits = fp32 value bits. Flag+value share one 64-bit word => relaxed ld/st OK.
// Epoch versioning => no init kernel: stale words decode as invalid this epoch.
__device__ unsigned long long g_state[MAX_TILES];
__device__ unsigned int g_ticket;   // zero-init once; monotonic across graph replays

__device__ __forceinline__ unsigned long long ld_state(const unsigned long long* p) {
    unsigned long long v;
    asm volatile("ld.global.cg.u64 %0, [%1];" : "=l"(v) : "l"(p));
    return v;
}
__device__ __forceinline__ void st_state(unsigned long long* p, unsigned long long v) {
    asm volatile("st.global.cg.u64 [%0], %1;" :: "l"(p), "l"(v) : "memory");
}
__device__ __forceinline__ unsigned long long pack_sv(unsigned st, float v) {
    return ((unsigned long long)st << 32) | (unsigned long long)__float_as_uint(v);
}

__global__ void __launch_bounds__(THREADS, 3) rtam_scan(
    const int* __restrict__ ann,
    const float* __restrict__ p_origin,
    const float* __restrict__ p_bd,
    const float* __restrict__ p_d,
    const float* __restrict__ p_s,
    const float* __restrict__ p_inc,
    const float* __restrict__ p_bi,
    float* __restrict__ out,
    int n, int ntiles)
{
    __shared__ float s_table[8];
    __shared__ float s_warp[NWARPS];
    __shared__ float s_excl;
    __shared__ unsigned s_ticket;

    const int tid  = threadIdx.x;
    const int lane = tid & 31;
    const int wid  = tid >> 5;

    if (tid == 0) {
        s_ticket = atomicAdd(&g_ticket, 1u);
        const float EPS = 0.05f;
        float bd = *p_bd, d = *p_d, s = *p_s, inc = *p_inc, bi = *p_bi;
        s_table[0] = 0.f;
        s_table[1] = fminf(bd, fminf(0.f, d)) - EPS;                 // big decrease
        s_table[2] = fminf(fmaxf(d, bd + EPS), -EPS);                // decrease (clip)
        s_table[3] = s;                                              // same
        s_table[4] = fminf(fmaxf(inc, EPS), bi - EPS);               // increase (clip)
        s_table[5] = fmaxf(bi, fmaxf(0.f, inc) + EPS);               // big increase
        s_table[6] = *p_origin;
    }
    __syncthreads();

    const unsigned ticket = s_ticket;
    const unsigned tile   = ticket % (unsigned)ntiles;
    const unsigned epoch  = ticket / (unsigned)ntiles;
    const unsigned eb     = epoch * 4u;               // status base for this epoch
    const float origin    = s_table[6];
    const long long base  = (long long)tile * TILE;
    const long long rem64 = (long long)n - base;
    const int remaining   = (rem64 > (long long)TILE) ? TILE : (int)rem64;

    // ---- per-thread blocked load + serial inclusive scan (16 items) ----
    float vals[ITEMS];
    float run = 0.f;

    if (remaining >= TILE) {
        const int4* in4 = (const int4*)(ann + base);
        #pragma unroll
        for (int k = 0; k < ITEMS / 4; k++) {
            int4 c = __ldcs(in4 + tid * (ITEMS / 4) + k);   // one-touch: evict-first
            run += s_table[c.x]; vals[4 * k + 0] = run;
            run += s_table[c.y]; vals[4 * k + 1] = run;
            run += s_table[c.z]; vals[4 * k + 2] = run;
            run += s_table[c.w]; vals[4 * k + 3] = run;
        }
    } else {
        #pragma unroll
        for (int j = 0; j < ITEMS; j++) {
            long long idx = base + (long long)tid * ITEMS + j;
            float c = (idx < (long long)n) ? s_table[ann[idx]] : 0.f;
            run += c;
            vals[j] = run;
        }
    }

    // ---- block scan of per-thread sums (warp shfl + smem across warps) ----
    const float tsum = run;
    float x = tsum;
    #pragma unroll
    for (int o = 1; o < 32; o <<= 1) {
        float y = __shfl_up_sync(0xFFFFFFFFu, x, o);
        if (lane >= o) x += y;
    }
    if (lane == 31) s_warp[wid] = x;
    __syncthreads();
    if (wid == 0) {
        float w = (lane < NWARPS) ? s_warp[lane] : 0.f;
        #pragma unroll
        for (int o = 1; o < NWARPS; o <<= 1) {
            float y = __shfl_up_sync(0xFFFFFFFFu, w, o);
            if (lane >= o) w += y;
        }
        if (lane < NWARPS) s_warp[lane] = w;
    }
    __syncthreads();

    const float block_agg   = s_warp[NWARPS - 1];
    const float thread_excl = (wid > 0 ? s_warp[wid - 1] : 0.f) + (x - tsum);

    // ---- warp 0: publish aggregate, decoupled lookback, publish prefix ----
    if (wid == 0) {
        if (lane == 0)
            st_state(&g_state[tile], pack_sv(eb + (tile == 0 ? 2u : 1u), block_agg));

        float excl = 0.f;
        if (tile > 0) {
            int look = (int)tile - 1;
            for (;;) {
                int idx = look - lane;
                unsigned d;       // 1 = aggregate, 2 = prefix, else invalid
                float val;
                if (idx >= 0) {
                    unsigned long long v = ld_state(&g_state[idx]);
                    d   = (unsigned)(v >> 32) - eb;   // stale epoch -> huge value
                    val = __uint_as_float((unsigned)(v & 0xFFFFFFFFULL));
                } else {
                    d = 2u; val = 0.f;
                }
                unsigned pm = __ballot_sync(0xFFFFFFFFu, d == 2u);
                unsigned am = __ballot_sync(0xFFFFFFFFu, d == 1u || d == 2u);
                if (pm) {
                    int p = __ffs(pm) - 1;   // closest predecessor with a full prefix
                    unsigned need = (p == 31) ? 0xFFFFFFFFu : ((1u << (p + 1)) - 1u);
                    if ((am & need) == need) {
                        float contrib = (lane <= p) ? val : 0.f;
                        #pragma unroll
                        for (int o = 16; o; o >>= 1)
                            contrib += __shfl_xor_sync(0xFFFFFFFFu, contrib, o);
                        excl += contrib;
                        break;
                    }
                } else if (am == 0xFFFFFFFFu) {
                    float contrib = val;     // window of 32 aggregates, keep walking
                    #pragma unroll
                    for (int o = 16; o; o >>= 1)
                        contrib += __shfl_xor_sync(0xFFFFFFFFu, contrib, o);
                    excl += contrib;
                    look -= 32;
                }
                // else: spin until predecessors publish
            }
            if (lane == 0)
                st_state(&g_state[tile], pack_sv(eb + 2u, excl + block_agg));
        }
        if (lane == 0) s_excl = excl;
    }
    __syncthreads();

    // pref == out[base + 16*tid] (inclusive sum through item base+16*tid-1, + origin)
    const float pref = origin + s_excl + thread_excl;

    // ---- aligned blocked stores: thread t owns out[base+16t .. base+16t+15] ----
    if (remaining >= TILE) {
        float4* o4 = (float4*)(out + base + tid * ITEMS);   // 16B-aligned
        float4 r;
        r.x = pref;                 r.y = pref + vals[0];
        r.z = pref + vals[1];       r.w = pref + vals[2];
        __stcs(o4 + 0, r);
        #pragma unroll
        for (int k = 0; k < 3; k++) {
            r.x = pref + vals[3 + 4 * k];
            r.y = pref + vals[4 + 4 * k];
            r.z = pref + vals[5 + 4 * k];
            r.w = pref + vals[6 + 4 * k];
            __stcs(o4 + 1 + k, r);
        }
        // the one output slot past this tile's range: out[n] when this is the last tile
        if (tid == THREADS - 1 && base + TILE == (long long)n)
            out[n] = pref + vals[15];
    } else {
        #pragma unroll
        for (int j = 0; j < ITEMS; j++) {
            int i = tid * ITEMS + j;
            if (i <= remaining)
                out[base + i] = pref + (j ? vals[j - 1] : 0.f);
        }
        // out[base + i] for i in [16*tid+16 ... ] handled by next thread's j=0;
        // the final element i == remaining is covered since remaining <= TILE-1 here.
    }
}

extern "C" void kernel_launch(void* const* d_in, const int* in_sizes, int n_in,
                              void* d_out, int out_size) {
    const int*   ann    = (const int*)d_in[0];
    const float* origin = (const float*)d_in[1];
    const float* bd     = (const float*)d_in[2];
    const float* d      = (const float*)d_in[3];
    const float* s      = (const float*)d_in[4];
    const float* inc    = (const float*)d_in[5];
    const float* bi     = (const float*)d_in[6];
    float* out = (float*)d_out;

    int n = in_sizes[0];
    int ntiles = (n + TILE - 1) / TILE;
    if (ntiles > MAX_TILES) ntiles = MAX_TILES;   // n = 2^25 -> 4096 tiles

    rtam_scan<<<ntiles, THREADS>>>(ann, origin, bd, d, s, inc, bi, out, n, ntiles);
}